// round 3
// baseline (speedup 1.0000x reference)
#include <cuda_runtime.h>

// Conv2d 3x3 VALID, C_in=C_out=8, 2048x2048 fp32 -> (8, 2046, 2046)
// Round 3: fp32x2 FMA conv, RF-bank-aware:
//  - inputs loaded as ulonglong2 + ull -> pairs (0,1),(2,3),(4,5) are free
//    even-aligned register pairs; only odd pairs (1,2),(3,4) constructed
//  - FMA emission groups instructions sharing the P operand consecutively
//    (same slot) so ptxas can set .reuse and cut RF bank pressure
//  - lower register footprint -> higher occupancy

#define CIN  8
#define COUT 8
#define IH   2048
#define IW   2048
#define OHH  2046
#define OWW  2046
#define CH   (IH * IW)

typedef unsigned long long ull;

__device__ __forceinline__ ull pack2(float lo, float hi) {
    ull r;
    asm("mov.b64 %0, {%1, %2};"
        : "=l"(r)
        : "r"(__float_as_uint(lo)), "r"(__float_as_uint(hi)));
    return r;
}

// pair = (hi word of x, lo word of y)
__device__ __forceinline__ ull pack_mid(ull x, ull y) {
    ull r;
    asm("{\n\t"
        ".reg .b32 xl, xh, yl, yh;\n\t"
        "mov.b64 {xl, xh}, %1;\n\t"
        "mov.b64 {yl, yh}, %2;\n\t"
        "mov.b64 %0, {xh, yl};\n\t"
        "}"
        : "=l"(r) : "l"(x), "l"(y));
    return r;
}

__device__ __forceinline__ ull fma2(ull a, ull b, ull c) {
    ull d;
    asm("fma.rn.f32x2 %0, %1, %2, %3;"
        : "=l"(d)
        : "l"(a), "l"(b), "l"(c));
    return d;
}

__global__ __launch_bounds__(128)
void conv3x3_f32x2_kernel(const float* __restrict__ x,
                          const float* __restrict__ w,
                          float* __restrict__ out) {
    // Packed (w, w) weights in shared: layout [cin][ky][kx][cout]
    __shared__ ull wsh[CIN * 9 * COUT];

    const int tid = threadIdx.y * 32 + threadIdx.x;
    for (int i = tid; i < CIN * 9 * COUT; i += 128) {
        int co   = i & 7;
        int rest = i >> 3;
        int kx   = rest % 3;
        int ky   = (rest / 3) % 3;
        int cin  = rest / 9;
        float wv = w[((co * CIN + cin) * 3 + ky) * 3 + kx];
        wsh[i] = pack2(wv, wv);
    }
    __syncthreads();

    const int tile_x = blockIdx.x * 32 + threadIdx.x;   // 0..511
    const int tile_y = blockIdx.y * 4  + threadIdx.y;
    const int y0 = tile_y * 2;
    if (y0 >= OHH) return;

    const int x0 = tile_x * 4;                 // 0..2044, 16B aligned
    const bool edge = (x0 >= OWW - 2);         // x0 == 2044
    const int boff = edge ? 2 : 4;             // edge: in-bounds dummy pair

    const float* ip = x + (size_t)y0 * IW + x0;

    // Current-cin inputs as aligned 64-bit pairs:
    // A2[r].x = (v0,v1), A2[r].y = (v2,v3), Bp[r] = (v4,v5)
    ulonglong2 A2[4];
    ull Bp[4];
    #pragma unroll
    for (int r = 0; r < 4; ++r) {
        A2[r] = *reinterpret_cast<const ulonglong2*>(ip + r * IW);
        Bp[r] = *reinterpret_cast<const ull*>(ip + r * IW + boff);
    }

    ull acc[COUT][2][2];
    #pragma unroll
    for (int co = 0; co < COUT; ++co)
        #pragma unroll
        for (int r = 0; r < 2; ++r) {
            acc[co][r][0] = 0ull;
            acc[co][r][1] = 0ull;
        }

    #pragma unroll
    for (int cin = 0; cin < CIN; ++cin) {
        // 5 overlapping pairs per row; 0/2/4 are register aliases, 1/3 built
        ull P[4][5];
        #pragma unroll
        for (int r = 0; r < 4; ++r) {
            P[r][0] = A2[r].x;
            P[r][2] = A2[r].y;
            P[r][4] = Bp[r];
            P[r][1] = pack_mid(A2[r].x, A2[r].y);
            P[r][3] = pack_mid(A2[r].y, Bp[r]);
        }

        // Prefetch next cin; FMA block below hides the latency
        if (cin + 1 < CIN) {
            const float* np = ip + (size_t)(cin + 1) * CH;
            #pragma unroll
            for (int r = 0; r < 4; ++r) {
                A2[r] = *reinterpret_cast<const ulonglong2*>(np + r * IW);
                Bp[r] = *reinterpret_cast<const ull*>(np + r * IW + boff);
            }
        }

        const ull* wp = &wsh[cin * 9 * COUT];
        #pragma unroll
        for (int ky = 0; ky < 3; ++ky) {
            #pragma unroll
            for (int kx = 0; kx < 3; ++kx) {
                #pragma unroll
                for (int cp = 0; cp < 4; ++cp) {
                    ulonglong2 w2 = *reinterpret_cast<const ulonglong2*>(
                        &wp[(ky * 3 + kx) * COUT + cp * 2]);
                    // Pairs sharing the same P operand emitted consecutively
                    // (slot-consistent) so ptxas can mark .reuse on P.
                    #pragma unroll
                    for (int r = 0; r < 2; ++r) {
                        ull p0 = P[r + ky][kx];
                        ull p1 = P[r + ky][kx + 2];
                        acc[cp*2  ][r][0] = fma2(p0, w2.x, acc[cp*2  ][r][0]);
                        acc[cp*2+1][r][0] = fma2(p0, w2.y, acc[cp*2+1][r][0]);
                        acc[cp*2  ][r][1] = fma2(p1, w2.x, acc[cp*2  ][r][1]);
                        acc[cp*2+1][r][1] = fma2(p1, w2.y, acc[cp*2+1][r][1]);
                    }
                }
            }
        }
    }

    // Store packed pairs; edge tile stores only cols 2044/2045
    #pragma unroll
    for (int co = 0; co < COUT; ++co) {
        #pragma unroll
        for (int r = 0; r < 2; ++r) {
            float* op = out + (size_t)co * (OHH * OWW) + (size_t)(y0 + r) * OWW + x0;
            union { ull u; float2 f; } c0, c1;
            c0.u = acc[co][r][0];
            *reinterpret_cast<float2*>(op) = c0.f;
            if (!edge) {
                c1.u = acc[co][r][1];
                *reinterpret_cast<float2*>(op + 2) = c1.f;
            }
        }
    }
}

extern "C" void kernel_launch(void* const* d_in, const int* in_sizes, int n_in,
                              void* d_out, int out_size) {
    const float* x = (const float*)d_in[0];   // (8, 2048, 2048) fp32
    const float* w = (const float*)d_in[1];   // (8, 8, 3, 3) fp32
    float* out = (float*)d_out;               // (8, 2046, 2046) fp32

    dim3 block(32, 4);
    dim3 grid(16, 256);
    conv3x3_f32x2_kernel<<<grid, block>>>(x, w, out);
}

// round 5
// speedup vs baseline: 1.2853x; 1.2853x over previous
#include <cuda_runtime.h>
#include <cuda_bf16.h>
#include <cstdint>

// Conv2d 3x3 VALID, C_in=C_out=8, 2048x2048 fp32 -> (8, 2046, 2046)
// Round 5: warp-level tensor cores via mma.sync.m16n8k16 (bf16, fp32 accum)
// -- baseline PTX, compiles for compute_103 (tcgen05 needs the 'a' target).
//
// Numerics: x = x_hi + x_lo (bf16 each), folded into K:
//   k even slot = x_hi, k odd slot = x_lo
//   B main: (w_hi, w_hi)  -> x_hi*w_hi + x_lo*w_hi
//   B corr: (w_lo, 0)     -> x_hi*w_lo
// dropped term x_lo*w_lo ~ 2^-18 relative.
//
// GEMM mapping per warp: M=16 output pixels, N=8 couts, K=16=(8 cin x hi/lo),
// accumulated over 9 taps (ky,kx) x 2 (main/corr) = 18 MMAs per chunk.
// Warp = one output row x 128 px = 8 chunks. Block = 4 rows x 128 px.

#define CIN   8
#define COUT  8
#define IH    2048
#define IW    2048
#define OHH   2046
#define OWW   2046
#define CH    (IH*IW)
#define TPX   128
#define TR    4
#define INR   6          // TR + 2 input rows
#define INPX  130        // TPX + 2 input pixels per row

typedef uint32_t u32;

__device__ __forceinline__ u32 bf16_hi_lo_pack(float v) {
    __nv_bfloat16 hb = __float2bfloat16(v);            // RN
    float hf = __bfloat162float(hb);
    __nv_bfloat16 lb = __float2bfloat16(v - hf);
    return (u32)__bfloat16_as_ushort(hb) | ((u32)__bfloat16_as_ushort(lb) << 16);
}

__device__ __forceinline__ void mma16816(float& d0, float& d1, float& d2, float& d3,
                                         u32 a0, u32 a1, u32 a2, u32 a3,
                                         u32 b0, u32 b1) {
    asm volatile(
        "mma.sync.aligned.m16n8k16.row.col.f32.bf16.bf16.f32 "
        "{%0,%1,%2,%3}, {%4,%5,%6,%7}, {%8,%9}, {%0,%1,%2,%3};"
        : "+f"(d0), "+f"(d1), "+f"(d2), "+f"(d3)
        : "r"(a0), "r"(a1), "r"(a2), "r"(a3), "r"(b0), "r"(b1));
}

__global__ __launch_bounds__(128)
void conv3x3_mma_kernel(const float* __restrict__ x,
                        const float* __restrict__ w,
                        float* __restrict__ out) {
    // stage[row][px][s]: s is cin interleaved so that (cin=q, cin=q+4) are the
    // adjacent words (2q, 2q+1) -> one LDS.64 yields a thread's (a_lo, a_hi8col)
    // fragment words. Pixel stride 32B; conflict-free per half-warp.
    __shared__ u32 stage[INR][INPX][8];

    const int tid  = threadIdx.x;
    const int wid  = tid >> 5;
    const int lane = tid & 31;
    const int gid  = lane >> 2;   // fragment row group / cout n
    const int q    = lane & 3;    // fragment k-pair / cin selector

    int x0 = blockIdx.x * TPX; if (x0 > OWW - TPX) x0 = OWW - TPX;
    int y0 = blockIdx.y * TR;  if (y0 > OHH - TR)  y0 = OHH - TR;

    // ---- weight fragments in registers: co = gid, cin = q (+4) ----
    u32 bm[9][2], bc[9][2];
    #pragma unroll
    for (int i = 0; i < 9; ++i) {
        int ky = i / 3, kx = i % 3;
        #pragma unroll
        for (int h = 0; h < 2; ++h) {
            int cin = q + 4 * h;
            float wv = __ldg(&w[((gid * CIN + cin) * 3 + ky) * 3 + kx]);
            __nv_bfloat16 hb = __float2bfloat16(wv);
            float hf = __bfloat162float(hb);
            __nv_bfloat16 lb = __float2bfloat16(wv - hf);
            u32 hu = __bfloat16_as_ushort(hb);
            u32 lu = __bfloat16_as_ushort(lb);
            bm[i][h] = hu | (hu << 16);   // (w_hi, w_hi)
            bc[i][h] = lu;                // (w_lo, 0)
        }
    }

    // ---- stage inputs: hi/lo split, cin-interleaved ----
    for (int it = tid; it < INR * INPX; it += 128) {
        int b  = it / INPX;
        int xl = it - b * INPX;
        const float* ip = x + (size_t)(y0 + b) * IW + (x0 + xl);
        u32 sv[8];
        #pragma unroll
        for (int c = 0; c < 8; ++c) {
            u32 pk = bf16_hi_lo_pack(__ldg(ip + (size_t)c * CH));
            sv[(c & 3) * 2 + (c >> 2)] = pk;
        }
        uint4* dst = reinterpret_cast<uint4*>(&stage[b][xl][0]);
        dst[0] = make_uint4(sv[0], sv[1], sv[2], sv[3]);
        dst[1] = make_uint4(sv[4], sv[5], sv[6], sv[7]);
    }
    __syncthreads();

    // ---- compute: warp wid handles output row y0+wid ----
    const size_t PL = (size_t)OHH * OWW;
    const int orow = y0 + wid;

    #pragma unroll 1
    for (int chunk = 0; chunk < 8; ++chunk) {
        float d0 = 0.f, d1 = 0.f, d2 = 0.f, d3 = 0.f;
        #pragma unroll
        for (int ky = 0; ky < 3; ++ky) {
            const u32* rowp = &stage[wid + ky][0][0];
            #pragma unroll
            for (int kx = 0; kx < 3; ++kx) {
                int px = chunk * 16 + gid + kx;
                uint2 lo  = *reinterpret_cast<const uint2*>(rowp + px * 8 + 2 * q);
                uint2 hi8 = *reinterpret_cast<const uint2*>(rowp + (px + 8) * 8 + 2 * q);
                int i = ky * 3 + kx;
                // a0={r,klo} a1={r+8,klo} a2={r,khi} a3={r+8,khi}
                mma16816(d0, d1, d2, d3, lo.x, hi8.x, lo.y, hi8.y, bm[i][0], bm[i][1]);
                mma16816(d0, d1, d2, d3, lo.x, hi8.x, lo.y, hi8.y, bc[i][0], bc[i][1]);
            }
        }
        // D: d0=D[gid][2q] d1=D[gid][2q+1] d2=D[gid+8][2q] d3=D[gid+8][2q+1]
        int pix = x0 + chunk * 16 + gid;
        float* op = out + (size_t)(2 * q) * PL + (size_t)orow * OWW + pix;
        op[0]      = d0;
        op[PL]     = d1;
        op[8]      = d2;
        op[PL + 8] = d3;
    }
}

extern "C" void kernel_launch(void* const* d_in, const int* in_sizes, int n_in,
                              void* d_out, int out_size) {
    const float* x = (const float*)d_in[0];   // (8, 2048, 2048) fp32
    const float* w = (const float*)d_in[1];   // (8, 8, 3, 3) fp32
    float* out = (float*)d_out;               // (8, 2046, 2046) fp32

    dim3 grid(16, 512);   // 16 x-tiles x 512 y-tiles, edges clamped
    conv3x3_mma_kernel<<<grid, 128>>>(x, w, out);
}